// round 9
// baseline (speedup 1.0000x reference)
#include <cuda_runtime.h>
#include <math.h>
#include <stdint.h>

// Problem constants (fixed shapes for this problem instance)
#define S_LEN  1024
#define DM     4096
#define NH     32
#define HD     128
#define CACHE  2048
#define TTOT   (CACHE + S_LEN)   // 3072 total kv positions

// Scratch (device globals: allocation-free rule)
__device__ float g_xn[S_LEN * DM];
__device__ float g_q [S_LEN * DM];
__device__ float g_k [S_LEN * DM];
__device__ float g_at[S_LEN * DM];
__device__ float g_kc[(size_t)TTOT * DM];   // tf32-rounded unified K [T,H,HD]
__device__ float g_vc[(size_t)TTOT * DM];   // tf32-rounded unified V [T,H,HD]
__device__ float g_wqc[(size_t)DM * DM];    // tf32-rounded weights
__device__ float g_wkc[(size_t)DM * DM];
__device__ float g_wvc[(size_t)DM * DM];
__device__ float g_woc[(size_t)DM * DM];

// ---------------------------------------------------------------------------
// Common tensor-core helpers
// ---------------------------------------------------------------------------
__device__ __forceinline__ uint32_t f2tf32(float x) {
    uint32_t r;
    asm("cvt.rna.tf32.f32 %0, %1;" : "=r"(r) : "f"(x));
    return r;
}

__device__ __forceinline__ void mma_tf32(float c[4], const uint32_t a[4], const uint32_t b[2]) {
    asm volatile(
        "mma.sync.aligned.m16n8k8.row.col.f32.tf32.tf32.f32 "
        "{%0,%1,%2,%3}, {%4,%5,%6,%7}, {%8,%9}, {%0,%1,%2,%3};"
        : "+f"(c[0]), "+f"(c[1]), "+f"(c[2]), "+f"(c[3])
        : "r"(a[0]), "r"(a[1]), "r"(a[2]), "r"(a[3]), "r"(b[0]), "r"(b[1]));
}

__device__ __forceinline__ void ldsm4(uint32_t r[4], uint32_t addr) {
    asm volatile("ldmatrix.sync.aligned.m8n8.x4.shared.b16 {%0,%1,%2,%3}, [%4];"
        : "=r"(r[0]), "=r"(r[1]), "=r"(r[2]), "=r"(r[3]) : "r"(addr));
}

__device__ __forceinline__ void cp16(uint32_t dst, const void* src) {
    asm volatile("cp.async.cg.shared.global [%0], [%1], 16;" :: "r"(dst), "l"(src));
}
#define CP_COMMIT()  asm volatile("cp.async.commit_group;")
#define CP_WAIT0()   asm volatile("cp.async.wait_group 0;")
#define CP_WAIT1()   asm volatile("cp.async.wait_group 1;")

// ---------------------------------------------------------------------------
// RMSNorm: one block per row (4096 elems), 256 threads. Emits rna tf32.
// ---------------------------------------------------------------------------
__global__ void rmsnorm_kernel(const float* __restrict__ xs,
                               const float* __restrict__ w)
{
    const int row = blockIdx.x;
    const int tid = threadIdx.x;
    const float* x = xs + (size_t)row * DM;
    float* y = g_xn + (size_t)row * DM;

    float ss = 0.f;
#pragma unroll
    for (int i = 0; i < 4; i++) {
        float4 v = *(const float4*)(x + (i * 256 + tid) * 4);
        ss += v.x * v.x + v.y * v.y + v.z * v.z + v.w * v.w;
    }
#pragma unroll
    for (int off = 16; off; off >>= 1)
        ss += __shfl_xor_sync(0xffffffffu, ss, off);

    __shared__ float red[8];
    __shared__ float s_inv;
    if ((tid & 31) == 0) red[tid >> 5] = ss;
    __syncthreads();
    if (tid == 0) {
        float t = 0.f;
#pragma unroll
        for (int i = 0; i < 8; i++) t += red[i];
        s_inv = rsqrtf(t / (float)DM + 1e-6f);
    }
    __syncthreads();
    const float inv = s_inv;
#pragma unroll
    for (int i = 0; i < 4; i++) {
        int base = (i * 256 + tid) * 4;
        float4 v = *(const float4*)(x + base);
        float4 g = *(const float4*)(w + base);
        uint4 u;
        u.x = f2tf32(v.x * inv * g.x);
        u.y = f2tf32(v.y * inv * g.y);
        u.z = f2tf32(v.z * inv * g.z);
        u.w = f2tf32(v.w * inv * g.w);
        *(uint4*)(y + base) = u;
    }
}

// ---------------------------------------------------------------------------
// Weight conversion: RNA-round all 4 weight matrices to tf32 buffers.
// ---------------------------------------------------------------------------
__global__ void convert_w_kernel(const float* __restrict__ wq,
                                 const float* __restrict__ wk,
                                 const float* __restrict__ wv,
                                 const float* __restrict__ wo)
{
    const size_t per = (size_t)DM * DM / 4;
    size_t i4 = (size_t)blockIdx.x * blockDim.x + threadIdx.x;
    int w = (int)(i4 / per);
    size_t off = (i4 - (size_t)w * per) * 4;
    const float* src = (w == 0) ? wq : (w == 1) ? wk : (w == 2) ? wv : wo;
    float* dst = (w == 0) ? g_wqc : (w == 1) ? g_wkc : (w == 2) ? g_wvc : g_woc;
    float4 v = *(const float4*)(src + off);
    uint4 u;
    u.x = f2tf32(v.x); u.y = f2tf32(v.y); u.z = f2tf32(v.z); u.w = f2tf32(v.w);
    *(uint4*)(dst + off) = u;
}

// ---------------------------------------------------------------------------
// TF32 tensor-core GEMM (NT): C[M,N] = A[M,K] * B[N,K]^T (round-7 proven).
// Tile 128x128x32, 3-stage cp.async, ldmatrix fragments, stride 36.
// ROUND: epilogue RNA-rounds output to tf32 (for the V projection, whose
// output is only ever consumed as an mma operand).
// ---------------------------------------------------------------------------
#define GSTR 36
#define ATW  (128 * GSTR)
#define STW  (2 * ATW)
#define NST  3
#define GEMM_SMEM_BYTES (NST * STW * 4)   // 110592 B

template <bool ROUND>
__global__ void __launch_bounds__(256, 2)
sgemm_tc(const float* __restrict__ A, const float* __restrict__ B,
         float* __restrict__ C, int N, int K)
{
    extern __shared__ uint32_t gsm[];
    const uint32_t sbase = (uint32_t)__cvta_generic_to_shared(gsm);

    const int tid  = threadIdx.x;
    const int lane = tid & 31;
    const int warp = tid >> 5;
    const int g    = lane >> 2;
    const int tig  = lane & 3;
    const int m_base = (warp >> 2) * 64;
    const int n_base = (warp & 3) * 32;

    const int r0 = tid >> 3;
    const int c0 = (tid & 7) << 2;
    const float* Ag = A + (size_t)(blockIdx.y * 128 + r0) * K + c0;
    const float* Bg = B + (size_t)(blockIdx.x * 128 + r0) * K + c0;
    const uint32_t d0 = (uint32_t)(r0 * GSTR + c0) * 4;
    const size_t gstep = (size_t)32 * K;
    const uint32_t sstep = (uint32_t)(32 * GSTR) * 4;

    auto issue = [&](int kt) {
        const uint32_t st = sbase + (uint32_t)(kt % NST) * (STW * 4);
        const int ko = kt << 5;
        const float* a = Ag + ko;
        const float* b = Bg + ko;
#pragma unroll
        for (int it = 0; it < 4; it++) {
            cp16(st + d0 + it * sstep, a + it * gstep);
            cp16(st + ATW * 4 + d0 + it * sstep, b + it * gstep);
        }
        CP_COMMIT();
    };

    float c[4][4][4];
#pragma unroll
    for (int mt = 0; mt < 4; mt++)
#pragma unroll
        for (int nt = 0; nt < 4; nt++)
#pragma unroll
            for (int i = 0; i < 4; i++) c[mt][nt][i] = 0.f;

    issue(0); issue(1);

    const int arow  = m_base + (lane & 15);
    const int acolh = (lane >> 2) & 4;
    const int brow  = n_base + (lane & 7) + ((lane >> 1) & 8);
    const int bcolh = (lane >> 1) & 4;

    const int KT = K >> 5;
    for (int kt = 0; kt < KT; kt++) {
        if (kt + 1 < KT) { CP_WAIT1(); } else { CP_WAIT0(); }
        __syncthreads();
        if (kt + 2 < KT) issue(kt + 2);

        const uint32_t tA = sbase + (uint32_t)(kt % NST) * (STW * 4);
        const uint32_t tB = tA + ATW * 4;
#pragma unroll
        for (int kk = 0; kk < 4; kk++) {
            uint32_t a[4][4], b[2][4];
#pragma unroll
            for (int mt = 0; mt < 4; mt++)
                ldsm4(a[mt], tA + (uint32_t)((arow + mt * 16) * GSTR + kk * 8 + acolh) * 4);
            ldsm4(b[0], tB + (uint32_t)(brow * GSTR + kk * 8 + bcolh) * 4);
            ldsm4(b[1], tB + (uint32_t)((brow + 16) * GSTR + kk * 8 + bcolh) * 4);
#pragma unroll
            for (int mt = 0; mt < 4; mt++)
#pragma unroll
                for (int nt = 0; nt < 4; nt++) {
                    uint32_t bb[2] = { b[nt >> 1][(nt & 1) * 2],
                                       b[nt >> 1][(nt & 1) * 2 + 1] };
                    mma_tf32(c[mt][nt], a[mt], bb);
                }
        }
    }

    const int crow = blockIdx.y * 128 + m_base + g;
    const int ccol = blockIdx.x * 128 + n_base + 2 * tig;
#pragma unroll
    for (int mt = 0; mt < 4; mt++) {
#pragma unroll
        for (int nt = 0; nt < 4; nt++) {
            const int row = crow + mt * 16;
            const int col = ccol + nt * 8;
            if (ROUND) {
                uint32_t* p0 = (uint32_t*)(C + (size_t)row * N + col);
                uint32_t* p1 = (uint32_t*)(C + (size_t)(row + 8) * N + col);
                p0[0] = f2tf32(c[mt][nt][0]);
                p0[1] = f2tf32(c[mt][nt][1]);
                p1[0] = f2tf32(c[mt][nt][2]);
                p1[1] = f2tf32(c[mt][nt][3]);
            } else {
                *(float2*)(C + (size_t)row * N + col) =
                    make_float2(c[mt][nt][0], c[mt][nt][1]);
                *(float2*)(C + (size_t)(row + 8) * N + col) =
                    make_float2(c[mt][nt][2], c[mt][nt][3]);
            }
        }
    }
}

// ---------------------------------------------------------------------------
// RoPE. rope_q: in-place on g_q (raw fp32). rope_k: g_k -> g_kc[CACHE:],
// RNA-rounded (bit-identical to round-7 rope-then-convert order).
// ---------------------------------------------------------------------------
__global__ void rope_q_kernel()
{
    int idx = blockIdx.x * blockDim.x + threadIdx.x;
    int i = idx & 63;
    int h = (idx >> 6) & (NH - 1);
    int s = idx >> 11;

    float pos = (float)(s + CACHE);
    float inv_freq = exp2f(-(float)i * (13.287712379549449f / 64.f));
    float ang = pos * inv_freq;
    float sn, cs;
    sincosf(ang, &sn, &cs);

    float* p = g_q + ((size_t)(s * NH + h) * HD) + i;
    float x1 = p[0];
    float x2 = p[64];
    p[0]  = x1 * cs - x2 * sn;
    p[64] = x2 * cs + x1 * sn;
}

__global__ void rope_k_kernel()
{
    int idx = blockIdx.x * blockDim.x + threadIdx.x;
    int i = idx & 63;
    int h = (idx >> 6) & (NH - 1);
    int s = idx >> 11;

    float pos = (float)(s + CACHE);
    float inv_freq = exp2f(-(float)i * (13.287712379549449f / 64.f));
    float ang = pos * inv_freq;
    float sn, cs;
    sincosf(ang, &sn, &cs);

    const float* p = g_k + ((size_t)(s * NH + h) * HD) + i;
    float x1 = p[0];
    float x2 = p[64];
    uint32_t* d = (uint32_t*)(g_kc + (size_t)(CACHE + s) * DM + h * HD + i);
    d[0]  = f2tf32(x1 * cs - x2 * sn);
    d[64] = f2tf32(x2 * cs + x1 * sn);
}

// ---------------------------------------------------------------------------
// Convert the KV-cache part (t < CACHE) into RNA-rounded tf32 buffers.
// (New-token K comes from rope_k; new-token V from the rounded V-GEMM.)
// ---------------------------------------------------------------------------
__global__ void convert_kv_cache_kernel(const float* __restrict__ cache_k,
                                        const float* __restrict__ cache_v)
{
    const size_t elem = ((size_t)blockIdx.x * blockDim.x + threadIdx.x) * 4;
    float4 k = *(const float4*)(cache_k + elem);
    float4 v = *(const float4*)(cache_v + elem);
    uint4 ko, vo;
    ko.x = f2tf32(k.x); ko.y = f2tf32(k.y); ko.z = f2tf32(k.z); ko.w = f2tf32(k.w);
    vo.x = f2tf32(v.x); vo.y = f2tf32(v.y); vo.z = f2tf32(v.z); vo.w = f2tf32(v.w);
    *(uint4*)(g_kc + elem) = ko;
    *(uint4*)(g_vc + elem) = vo;
}

// ---------------------------------------------------------------------------
// Tensor-core flash attention (round-7 core). Persistent 2-job blocks:
// grid = 256, block b runs jobs b and 511-b (paired long+short -> constant
// 81 tile-units per block, single clean wave).
// ---------------------------------------------------------------------------
#define KQSTR 132
#define VSTR  136
#define PSTR  68

#define QS_WORDS (64 * KQSTR)
#define KS_WORDS (64 * KQSTR)
#define VS_WORDS (64 * VSTR)
#define PS_WORDS (64 * PSTR)

#define FLASH_SMEM_WORDS (QS_WORDS + 2*KS_WORDS + 2*VS_WORDS + PS_WORDS + 192)
#define FLASH_SMEM_BYTES (FLASH_SMEM_WORDS * 4)

__global__ void __launch_bounds__(256)
flash_tc_kernel()
{
    extern __shared__ uint32_t fsm[];
    uint32_t* Qs  = fsm;
    uint32_t* Ks0 = Qs  + QS_WORDS;
    uint32_t* Ks1 = Ks0 + KS_WORDS;
    uint32_t* Vs0 = Ks1 + KS_WORDS;
    uint32_t* Vs1 = Vs0 + VS_WORDS;
    uint32_t* Ps  = Vs1 + VS_WORDS;
    float* m_s    = (float*)(Ps + PS_WORDS);
    float* l_s    = m_s + 64;
    float* salpha = l_s + 64;
    float* PsF    = (float*)Ps;

    const int tid = threadIdx.x;
    const int lane = tid & 31;
    const int warp = tid >> 5;
    const int g    = lane >> 2;
    const int tig  = lane & 3;
    const int wr   = warp >> 1;
    const int wc   = warp & 1;
    const int m0   = wr * 16;

    const uint32_t qs_a  = (uint32_t)__cvta_generic_to_shared(Qs);
    const uint32_t ks0_a = (uint32_t)__cvta_generic_to_shared(Ks0);
    const uint32_t ks1_a = (uint32_t)__cvta_generic_to_shared(Ks1);
    const uint32_t vs0_a = (uint32_t)__cvta_generic_to_shared(Vs0);
    const uint32_t vs1_a = (uint32_t)__cvta_generic_to_shared(Vs1);
    const uint32_t ps_a  = (uint32_t)__cvta_generic_to_shared(Ps);

    const int arow  = m0 + (lane & 15);
    const int acolh = (lane >> 2) & 4;
    const int brow  = wc * 32 + (lane & 7) + ((lane >> 1) & 8);
    const int bcolh = (lane >> 1) & 4;

    const float qscale = 0.08838834764831845f;

    for (int jj = 0; jj < 2; jj++) {
        const int id = jj ? (511 - (int)blockIdx.x) : (int)blockIdx.x;
        const int h  = id & (NH - 1);
        const int qt = (S_LEN / 64 - 1) - (id >> 5);

        // ---- Load Q tile (scaled, rna tf32) ----
#pragma unroll
        for (int it = 0; it < 8; it++) {
            int idx = it * 256 + tid;
            int r = idx >> 5;
            int c = (idx & 31) << 2;
            float4 v = *(const float4*)(g_q + (size_t)(qt * 64 + r) * DM + h * HD + c);
            uint4 u;
            u.x = f2tf32(v.x * qscale);
            u.y = f2tf32(v.y * qscale);
            u.z = f2tf32(v.z * qscale);
            u.w = f2tf32(v.w * qscale);
            *(uint4*)&Qs[r * KQSTR + c] = u;
        }
        if (tid < 64) { m_s[tid] = -1e30f; l_s[tid] = 0.f; }

        auto issue_kv = [&](int kt, int b) {
            const int t0 = kt * 64;
            const uint32_t ka = b ? ks1_a : ks0_a;
            const uint32_t va = b ? vs1_a : vs0_a;
#pragma unroll
            for (int it = 0; it < 8; it++) {
                int idx = it * 256 + tid;
                int r = idx >> 5;
                int c = (idx & 31) << 2;
                size_t off = (size_t)(t0 + r) * DM + h * HD + c;
                cp16(ka + (r * KQSTR + c) * 4, g_kc + off);
                cp16(va + (r * VSTR  + c) * 4, g_vc + off);
            }
            CP_COMMIT();
        };

        issue_kv(0, 0);

        float oacc[8][4];
#pragma unroll
        for (int nt = 0; nt < 8; nt++)
#pragma unroll
            for (int i = 0; i < 4; i++) oacc[nt][i] = 0.f;

        const int ntiles = 33 + qt;
        int p = 0;
        for (int kt = 0; kt < ntiles; kt++) {
            CP_WAIT0();
            __syncthreads();
            if (kt + 1 < ntiles) issue_kv(kt + 1, p ^ 1);

            const uint32_t ka = p ? ks1_a : ks0_a;
            const uint32_t* Vc = p ? Vs1 : Vs0;

            // ---- S = Q K^T (warp tile 16x32), ldmatrix fragments ----
            float sacc[4][4];
#pragma unroll
            for (int nt = 0; nt < 4; nt++)
#pragma unroll
                for (int i = 0; i < 4; i++) sacc[nt][i] = 0.f;

#pragma unroll
            for (int ks = 0; ks < 16; ks++) {
                const int k0 = ks * 8;
                uint32_t a[4], b[2][4];
                ldsm4(a, qs_a + (uint32_t)(arow * KQSTR + k0 + acolh) * 4);
                ldsm4(b[0], ka + (uint32_t)(brow * KQSTR + k0 + bcolh) * 4);
                ldsm4(b[1], ka + (uint32_t)((brow + 16) * KQSTR + k0 + bcolh) * 4);
#pragma unroll
                for (int nt = 0; nt < 4; nt++) {
                    uint32_t bb[2] = { b[nt >> 1][(nt & 1) * 2],
                                       b[nt >> 1][(nt & 1) * 2 + 1] };
                    mma_tf32(sacc[nt], a, bb);
                }
            }

            const bool diag = (kt == ntiles - 1);
            const int r0 = m0 + g, r1 = m0 + g + 8;
#pragma unroll
            for (int nt = 0; nt < 4; nt++) {
                int col = wc * 32 + nt * 8 + 2 * tig;
                float v0 = sacc[nt][0], v1 = sacc[nt][1];
                float v2 = sacc[nt][2], v3 = sacc[nt][3];
                if (diag) {
                    if (col     > r0) v0 = -1e30f;
                    if (col + 1 > r0) v1 = -1e30f;
                    if (col     > r1) v2 = -1e30f;
                    if (col + 1 > r1) v3 = -1e30f;
                }
                *(float2*)&PsF[r0 * PSTR + col] = make_float2(v0, v1);
                *(float2*)&PsF[r1 * PSTR + col] = make_float2(v2, v3);
            }
            __syncthreads();

            // ---- online softmax: 4 threads per row ----
            {
                const int row = tid >> 2;
                const int qd  = tid & 3;
                float* pr = PsF + row * PSTR + qd * 16;
                float4 x0 = *(float4*)(pr + 0);
                float4 x1 = *(float4*)(pr + 4);
                float4 x2 = *(float4*)(pr + 8);
                float4 x3 = *(float4*)(pr + 12);
                float mp = fmaxf(fmaxf(fmaxf(x0.x, x0.y), fmaxf(x0.z, x0.w)),
                                 fmaxf(fmaxf(x1.x, x1.y), fmaxf(x1.z, x1.w)));
                mp = fmaxf(mp, fmaxf(fmaxf(fmaxf(x2.x, x2.y), fmaxf(x2.z, x2.w)),
                                     fmaxf(fmaxf(x3.x, x3.y), fmaxf(x3.z, x3.w))));
                mp = fmaxf(mp, __shfl_xor_sync(0xffffffffu, mp, 1));
                mp = fmaxf(mp, __shfl_xor_sync(0xffffffffu, mp, 2));
                const float mold = m_s[row];
                const float mx = fmaxf(mold, mp);
                float sum;
                {
                    uint4 u;
                    float s = 0.f;
                    float p0, p1, p2, p3;
                    p0 = __expf(x0.x - mx); p1 = __expf(x0.y - mx);
                    p2 = __expf(x0.z - mx); p3 = __expf(x0.w - mx);
                    s += (p0 + p1) + (p2 + p3);
                    u.x = f2tf32(p0); u.y = f2tf32(p1); u.z = f2tf32(p2); u.w = f2tf32(p3);
                    *(uint4*)(pr + 0) = u;
                    p0 = __expf(x1.x - mx); p1 = __expf(x1.y - mx);
                    p2 = __expf(x1.z - mx); p3 = __expf(x1.w - mx);
                    s += (p0 + p1) + (p2 + p3);
                    u.x = f2tf32(p0); u.y = f2tf32(p1); u.z = f2tf32(p2); u.w = f2tf32(p3);
                    *(uint4*)(pr + 4) = u;
                    p0 = __expf(x2.x - mx); p1 = __expf(x2.y - mx);
                    p2 = __expf(x2.z - mx); p3 = __expf(x2.w - mx);
                    s += (p0 + p1) + (p2 + p3);
                    u.x = f2tf32(p0); u.y = f2tf32(p1); u.z = f2tf32(p2); u.w = f2tf32(p3);
                    *(uint4*)(pr + 8) = u;
                    p0 = __expf(x3.x - mx); p1 = __expf(x3.y - mx);
                    p2 = __expf(x3.z - mx); p3 = __expf(x3.w - mx);
                    s += (p0 + p1) + (p2 + p3);
                    u.x = f2tf32(p0); u.y = f2tf32(p1); u.z = f2tf32(p2); u.w = f2tf32(p3);
                    *(uint4*)(pr + 12) = u;
                    sum = s;
                }
                sum += __shfl_xor_sync(0xffffffffu, sum, 1);
                sum += __shfl_xor_sync(0xffffffffu, sum, 2);
                __syncwarp();
                if (qd == 0) {
                    float alpha = __expf(mold - mx);
                    l_s[row] = l_s[row] * alpha + sum;
                    m_s[row] = mx;
                    salpha[row] = alpha;
                }
            }
            __syncthreads();

            // ---- rescale O, then O += P V (warp tile 16x64) ----
            {
                const float alo = salpha[m0 + g];
                const float ahi = salpha[m0 + g + 8];
#pragma unroll
                for (int nt = 0; nt < 8; nt++) {
                    oacc[nt][0] *= alo; oacc[nt][1] *= alo;
                    oacc[nt][2] *= ahi; oacc[nt][3] *= ahi;
                }
#pragma unroll
                for (int ks = 0; ks < 8; ks++) {
                    const int k0 = ks * 8;
                    uint32_t a[4];
                    ldsm4(a, ps_a + (uint32_t)(arow * PSTR + k0 + acolh) * 4);
                    const uint32_t* V0 = Vc + (k0 + tig) * VSTR + wc * 64 + g;
                    const uint32_t* V1 = V0 + 4 * VSTR;
#pragma unroll
                    for (int nt = 0; nt < 8; nt++) {
                        uint32_t b[2];
                        b[0] = V0[nt * 8];
                        b[1] = V1[nt * 8];
                        mma_tf32(oacc[nt], a, b);
                    }
                }
            }
            p ^= 1;
        }

        // ---- epilogue: O / l -> g_at (tf32-rounded; consumed only by GEMM) ----
        __syncthreads();
        const float ilo = 1.f / l_s[m0 + g];
        const float ihi = 1.f / l_s[m0 + g + 8];
        const int grow = qt * 64 + m0 + g;
#pragma unroll
        for (int nt = 0; nt < 8; nt++) {
            const int col = h * HD + wc * 64 + nt * 8 + 2 * tig;
            uint32_t* d0 = (uint32_t*)(g_at + (size_t)grow * DM + col);
            uint32_t* d1 = (uint32_t*)(g_at + (size_t)(grow + 8) * DM + col);
            d0[0] = f2tf32(oacc[nt][0] * ilo);
            d0[1] = f2tf32(oacc[nt][1] * ilo);
            d1[0] = f2tf32(oacc[nt][2] * ihi);
            d1[1] = f2tf32(oacc[nt][3] * ihi);
        }
        __syncthreads();   // smem reuse barrier before next job
    }
}

// ---------------------------------------------------------------------------
// Launch
// ---------------------------------------------------------------------------
extern "C" void kernel_launch(void* const* d_in, const int* in_sizes, int n_in,
                              void* d_out, int out_size)
{
    (void)in_sizes; (void)n_in; (void)out_size;
    const float* xs      = (const float*)d_in[0];
    const float* cache_k = (const float*)d_in[1];
    const float* cache_v = (const float*)d_in[2];
    const float* norm_w  = (const float*)d_in[3];
    const float* wq      = (const float*)d_in[4];
    const float* wk      = (const float*)d_in[5];
    const float* wv      = (const float*)d_in[6];
    const float* wo      = (const float*)d_in[7];
    float* out = (float*)d_out;

    float *p_xn, *p_q, *p_k, *p_at, *p_kc, *p_vc;
    float *p_wqc, *p_wkc, *p_wvc, *p_woc;
    cudaGetSymbolAddress((void**)&p_xn, g_xn);
    cudaGetSymbolAddress((void**)&p_q,  g_q);
    cudaGetSymbolAddress((void**)&p_k,  g_k);
    cudaGetSymbolAddress((void**)&p_at, g_at);
    cudaGetSymbolAddress((void**)&p_kc, g_kc);
    cudaGetSymbolAddress((void**)&p_vc, g_vc);
    cudaGetSymbolAddress((void**)&p_wqc, g_wqc);
    cudaGetSymbolAddress((void**)&p_wkc, g_wkc);
    cudaGetSymbolAddress((void**)&p_wvc, g_wvc);
    cudaGetSymbolAddress((void**)&p_woc, g_woc);

    cudaFuncSetAttribute(sgemm_tc<false>,
                         cudaFuncAttributeMaxDynamicSharedMemorySize,
                         GEMM_SMEM_BYTES);
    cudaFuncSetAttribute(sgemm_tc<true>,
                         cudaFuncAttributeMaxDynamicSharedMemorySize,
                         GEMM_SMEM_BYTES);
    cudaFuncSetAttribute(flash_tc_kernel,
                         cudaFuncAttributeMaxDynamicSharedMemorySize,
                         FLASH_SMEM_BYTES);

    // 1) RMSNorm (emits tf32-rounded xn)
    rmsnorm_kernel<<<S_LEN, 256>>>(xs, norm_w);

    // 2) Weight conversion to tf32 (all 4)
    {
        const size_t n4 = (size_t)4 * DM * DM / 4;
        convert_w_kernel<<<(unsigned)(n4 / 256), 256>>>(wq, wk, wv, wo);
    }

    // 3) KV-cache conversion (can run any time before flash)
    {
        const size_t n4 = (size_t)CACHE * DM / 4;
        convert_kv_cache_kernel<<<(unsigned)(n4 / 256), 256>>>(cache_k, cache_v);
    }

    // 4) QKV projections; V written rounded directly into g_vc[CACHE:]
    dim3 gg(DM / 128, S_LEN / 128);
    sgemm_tc<false><<<gg, 256, GEMM_SMEM_BYTES>>>(p_xn, p_wqc, p_q, DM, DM);
    sgemm_tc<false><<<gg, 256, GEMM_SMEM_BYTES>>>(p_xn, p_wkc, p_k, DM, DM);
    sgemm_tc<true ><<<gg, 256, GEMM_SMEM_BYTES>>>(p_xn, p_wvc,
                                                  p_vc + (size_t)CACHE * DM, DM, DM);

    // 5) RoPE: q in-place; k -> rounded into g_kc[CACHE:]
    const int rope_threads = S_LEN * NH * 64;
    rope_q_kernel<<<rope_threads / 256, 256>>>();
    rope_k_kernel<<<rope_threads / 256, 256>>>();

    // 6) Tensor-core flash attention (persistent paired jobs, 1 wave)
    flash_tc_kernel<<<256, 256, FLASH_SMEM_BYTES>>>();

    // 7) Output projection -> d_out
    sgemm_tc<false><<<gg, 256, GEMM_SMEM_BYTES>>>(p_at, p_woc, out, DM, DM);
}

// round 10
// speedup vs baseline: 1.0371x; 1.0371x over previous
#include <cuda_runtime.h>
#include <math.h>
#include <stdint.h>

// Problem constants (fixed shapes for this problem instance)
#define S_LEN  1024
#define DM     4096
#define NH     32
#define HD     128
#define CACHE  2048
#define TTOT   (CACHE + S_LEN)   // 3072 total kv positions

// Scratch (device globals: allocation-free rule)
__device__ float g_xn[S_LEN * DM];
__device__ float g_q [S_LEN * DM];
__device__ float g_k [S_LEN * DM];
__device__ float g_at[S_LEN * DM];
__device__ float g_kc[(size_t)TTOT * DM];     // tf32-rounded unified K [T,H,HD]
__device__ float g_vc[(size_t)TTOT * DM];     // tf32-rounded unified V [T,H,HD]
__device__ float g_wqkv[(size_t)3 * DM * DM]; // tf32-rounded stacked wq|wk|wv
__device__ float g_woc[(size_t)DM * DM];      // tf32-rounded wo

// ---------------------------------------------------------------------------
// Common tensor-core helpers
// ---------------------------------------------------------------------------
__device__ __forceinline__ uint32_t f2tf32(float x) {
    uint32_t r;
    asm("cvt.rna.tf32.f32 %0, %1;" : "=r"(r) : "f"(x));
    return r;
}

__device__ __forceinline__ void mma_tf32(float c[4], const uint32_t a[4], const uint32_t b[2]) {
    asm volatile(
        "mma.sync.aligned.m16n8k8.row.col.f32.tf32.tf32.f32 "
        "{%0,%1,%2,%3}, {%4,%5,%6,%7}, {%8,%9}, {%0,%1,%2,%3};"
        : "+f"(c[0]), "+f"(c[1]), "+f"(c[2]), "+f"(c[3])
        : "r"(a[0]), "r"(a[1]), "r"(a[2]), "r"(a[3]), "r"(b[0]), "r"(b[1]));
}

__device__ __forceinline__ void ldsm4(uint32_t r[4], uint32_t addr) {
    asm volatile("ldmatrix.sync.aligned.m8n8.x4.shared.b16 {%0,%1,%2,%3}, [%4];"
        : "=r"(r[0]), "=r"(r[1]), "=r"(r[2]), "=r"(r[3]) : "r"(addr));
}

__device__ __forceinline__ void cp16(uint32_t dst, const void* src) {
    asm volatile("cp.async.cg.shared.global [%0], [%1], 16;" :: "r"(dst), "l"(src));
}
#define CP_COMMIT()  asm volatile("cp.async.commit_group;")
#define CP_WAIT0()   asm volatile("cp.async.wait_group 0;")
#define CP_WAIT1()   asm volatile("cp.async.wait_group 1;")

// ---------------------------------------------------------------------------
// RMSNorm: one block per row (4096 elems), 256 threads. Emits rna tf32.
// ---------------------------------------------------------------------------
__global__ void rmsnorm_kernel(const float* __restrict__ xs,
                               const float* __restrict__ w)
{
    const int row = blockIdx.x;
    const int tid = threadIdx.x;
    const float* x = xs + (size_t)row * DM;
    float* y = g_xn + (size_t)row * DM;

    float ss = 0.f;
#pragma unroll
    for (int i = 0; i < 4; i++) {
        float4 v = *(const float4*)(x + (i * 256 + tid) * 4);
        ss += v.x * v.x + v.y * v.y + v.z * v.z + v.w * v.w;
    }
#pragma unroll
    for (int off = 16; off; off >>= 1)
        ss += __shfl_xor_sync(0xffffffffu, ss, off);

    __shared__ float red[8];
    __shared__ float s_inv;
    if ((tid & 31) == 0) red[tid >> 5] = ss;
    __syncthreads();
    if (tid == 0) {
        float t = 0.f;
#pragma unroll
        for (int i = 0; i < 8; i++) t += red[i];
        s_inv = rsqrtf(t / (float)DM + 1e-6f);
    }
    __syncthreads();
    const float inv = s_inv;
#pragma unroll
    for (int i = 0; i < 4; i++) {
        int base = (i * 256 + tid) * 4;
        float4 v = *(const float4*)(x + base);
        float4 g = *(const float4*)(w + base);
        uint4 u;
        u.x = f2tf32(v.x * inv * g.x);
        u.y = f2tf32(v.y * inv * g.y);
        u.z = f2tf32(v.z * inv * g.z);
        u.w = f2tf32(v.w * inv * g.w);
        *(uint4*)(y + base) = u;
    }
}

// ---------------------------------------------------------------------------
// Weight conversion: RNA-round weights. wq|wk|wv stacked into g_wqkv; wo
// into g_woc.
// ---------------------------------------------------------------------------
__global__ void convert_w_kernel(const float* __restrict__ wq,
                                 const float* __restrict__ wk,
                                 const float* __restrict__ wv,
                                 const float* __restrict__ wo)
{
    const size_t per = (size_t)DM * DM / 4;
    size_t i4 = (size_t)blockIdx.x * blockDim.x + threadIdx.x;
    int w = (int)(i4 / per);
    size_t off = (i4 - (size_t)w * per) * 4;
    const float* src = (w == 0) ? wq : (w == 1) ? wk : (w == 2) ? wv : wo;
    float* dst = (w == 3) ? g_woc : (g_wqkv + (size_t)w * DM * DM);
    float4 v = *(const float4*)(src + off);
    uint4 u;
    u.x = f2tf32(v.x); u.y = f2tf32(v.y); u.z = f2tf32(v.z); u.w = f2tf32(v.w);
    *(uint4*)(dst + off) = u;
}

// ---------------------------------------------------------------------------
// TF32 tensor-core GEMM (NT), round-7 proven core: tile 128x128x32,
// 3-stage cp.async, ldmatrix fragments, stride 36.
// FUSED variant: grid.x covers 3 stacked weight matrices (bx/32 selects
// B matrix and C destination; the V third is RNA-rounded on store).
// ---------------------------------------------------------------------------
#define GSTR 36
#define ATW  (128 * GSTR)
#define STW  (2 * ATW)
#define NST  3
#define GEMM_SMEM_BYTES (NST * STW * 4)   // 110592 B

template <bool FUSED, bool ROUND>
__global__ void __launch_bounds__(256, 2)
sgemm_tc(const float* __restrict__ A, const float* __restrict__ B_,
         float* __restrict__ C_, float* __restrict__ CV, int N, int K)
{
    extern __shared__ uint32_t gsm[];
    const uint32_t sbase = (uint32_t)__cvta_generic_to_shared(gsm);

    const int tid  = threadIdx.x;
    const int lane = tid & 31;
    const int warp = tid >> 5;
    const int g    = lane >> 2;
    const int tig  = lane & 3;
    const int m_base = (warp >> 2) * 64;
    const int n_base = (warp & 3) * 32;

    const float* B = B_;
    float* C = C_;
    int bxx = blockIdx.x;
    bool round_out = ROUND;
    if (FUSED) {
        const int third = blockIdx.x >> 5;       // 0:q 1:k 2:v
        bxx = blockIdx.x & 31;
        B = B_ + (size_t)third * DM * DM;
        if (third == 1) C = g_k;
        else if (third == 2) { C = CV; round_out = true; }
    }

    const int r0 = tid >> 3;
    const int c0 = (tid & 7) << 2;
    const float* Ag = A + (size_t)(blockIdx.y * 128 + r0) * K + c0;
    const float* Bg = B + (size_t)(bxx * 128 + r0) * K + c0;
    const uint32_t d0 = (uint32_t)(r0 * GSTR + c0) * 4;
    const size_t gstep = (size_t)32 * K;
    const uint32_t sstep = (uint32_t)(32 * GSTR) * 4;

    auto issue = [&](int kt) {
        const uint32_t st = sbase + (uint32_t)(kt % NST) * (STW * 4);
        const int ko = kt << 5;
        const float* a = Ag + ko;
        const float* b = Bg + ko;
#pragma unroll
        for (int it = 0; it < 4; it++) {
            cp16(st + d0 + it * sstep, a + it * gstep);
            cp16(st + ATW * 4 + d0 + it * sstep, b + it * gstep);
        }
        CP_COMMIT();
    };

    float c[4][4][4];
#pragma unroll
    for (int mt = 0; mt < 4; mt++)
#pragma unroll
        for (int nt = 0; nt < 4; nt++)
#pragma unroll
            for (int i = 0; i < 4; i++) c[mt][nt][i] = 0.f;

    issue(0); issue(1);

    const int arow  = m_base + (lane & 15);
    const int acolh = (lane >> 2) & 4;
    const int brow  = n_base + (lane & 7) + ((lane >> 1) & 8);
    const int bcolh = (lane >> 1) & 4;

    const int KT = K >> 5;
    for (int kt = 0; kt < KT; kt++) {
        if (kt + 1 < KT) { CP_WAIT1(); } else { CP_WAIT0(); }
        __syncthreads();
        if (kt + 2 < KT) issue(kt + 2);

        const uint32_t tA = sbase + (uint32_t)(kt % NST) * (STW * 4);
        const uint32_t tB = tA + ATW * 4;
#pragma unroll
        for (int kk = 0; kk < 4; kk++) {
            uint32_t a[4][4], b[2][4];
#pragma unroll
            for (int mt = 0; mt < 4; mt++)
                ldsm4(a[mt], tA + (uint32_t)((arow + mt * 16) * GSTR + kk * 8 + acolh) * 4);
            ldsm4(b[0], tB + (uint32_t)(brow * GSTR + kk * 8 + bcolh) * 4);
            ldsm4(b[1], tB + (uint32_t)((brow + 16) * GSTR + kk * 8 + bcolh) * 4);
#pragma unroll
            for (int mt = 0; mt < 4; mt++)
#pragma unroll
                for (int nt = 0; nt < 4; nt++) {
                    uint32_t bb[2] = { b[nt >> 1][(nt & 1) * 2],
                                       b[nt >> 1][(nt & 1) * 2 + 1] };
                    mma_tf32(c[mt][nt], a[mt], bb);
                }
        }
    }

    const int crow = blockIdx.y * 128 + m_base + g;
    const int ccol = bxx * 128 + n_base + 2 * tig;
#pragma unroll
    for (int mt = 0; mt < 4; mt++) {
#pragma unroll
        for (int nt = 0; nt < 4; nt++) {
            const int row = crow + mt * 16;
            const int col = ccol + nt * 8;
            if (round_out) {
                uint32_t* p0 = (uint32_t*)(C + (size_t)row * N + col);
                uint32_t* p1 = (uint32_t*)(C + (size_t)(row + 8) * N + col);
                p0[0] = f2tf32(c[mt][nt][0]);
                p0[1] = f2tf32(c[mt][nt][1]);
                p1[0] = f2tf32(c[mt][nt][2]);
                p1[1] = f2tf32(c[mt][nt][3]);
            } else {
                *(float2*)(C + (size_t)row * N + col) =
                    make_float2(c[mt][nt][0], c[mt][nt][1]);
                *(float2*)(C + (size_t)(row + 8) * N + col) =
                    make_float2(c[mt][nt][2], c[mt][nt][3]);
            }
        }
    }
}

// ---------------------------------------------------------------------------
// RoPE. rope_q: in-place on g_q (raw fp32). rope_k: g_k -> g_kc[CACHE:],
// RNA-rounded.
// ---------------------------------------------------------------------------
__global__ void rope_q_kernel()
{
    int idx = blockIdx.x * blockDim.x + threadIdx.x;
    int i = idx & 63;
    int h = (idx >> 6) & (NH - 1);
    int s = idx >> 11;

    float pos = (float)(s + CACHE);
    float inv_freq = exp2f(-(float)i * (13.287712379549449f / 64.f));
    float ang = pos * inv_freq;
    float sn, cs;
    sincosf(ang, &sn, &cs);

    float* p = g_q + ((size_t)(s * NH + h) * HD) + i;
    float x1 = p[0];
    float x2 = p[64];
    p[0]  = x1 * cs - x2 * sn;
    p[64] = x2 * cs + x1 * sn;
}

__global__ void rope_k_kernel()
{
    int idx = blockIdx.x * blockDim.x + threadIdx.x;
    int i = idx & 63;
    int h = (idx >> 6) & (NH - 1);
    int s = idx >> 11;

    float pos = (float)(s + CACHE);
    float inv_freq = exp2f(-(float)i * (13.287712379549449f / 64.f));
    float ang = pos * inv_freq;
    float sn, cs;
    sincosf(ang, &sn, &cs);

    const float* p = g_k + ((size_t)(s * NH + h) * HD) + i;
    float x1 = p[0];
    float x2 = p[64];
    uint32_t* d = (uint32_t*)(g_kc + (size_t)(CACHE + s) * DM + h * HD + i);
    d[0]  = f2tf32(x1 * cs - x2 * sn);
    d[64] = f2tf32(x2 * cs + x1 * sn);
}

// ---------------------------------------------------------------------------
// Convert the KV-cache part (t < CACHE) into RNA-rounded tf32 buffers.
// ---------------------------------------------------------------------------
__global__ void convert_kv_cache_kernel(const float* __restrict__ cache_k,
                                        const float* __restrict__ cache_v)
{
    const size_t elem = ((size_t)blockIdx.x * blockDim.x + threadIdx.x) * 4;
    float4 k = *(const float4*)(cache_k + elem);
    float4 v = *(const float4*)(cache_v + elem);
    uint4 ko, vo;
    ko.x = f2tf32(k.x); ko.y = f2tf32(k.y); ko.z = f2tf32(k.z); ko.w = f2tf32(k.w);
    vo.x = f2tf32(v.x); vo.y = f2tf32(v.y); vo.z = f2tf32(v.z); vo.w = f2tf32(v.w);
    *(uint4*)(g_kc + elem) = ko;
    *(uint4*)(g_vc + elem) = vo;
}

// ---------------------------------------------------------------------------
// Tensor-core flash attention (round-7 proven scheduling: 512 one-job
// blocks, long jobs first).
// ---------------------------------------------------------------------------
#define KQSTR 132
#define VSTR  136
#define PSTR  68

#define QS_WORDS (64 * KQSTR)
#define KS_WORDS (64 * KQSTR)
#define VS_WORDS (64 * VSTR)
#define PS_WORDS (64 * PSTR)

#define FLASH_SMEM_WORDS (QS_WORDS + 2*KS_WORDS + 2*VS_WORDS + PS_WORDS + 192)
#define FLASH_SMEM_BYTES (FLASH_SMEM_WORDS * 4)

__global__ void __launch_bounds__(256, 1)
flash_tc_kernel()
{
    extern __shared__ uint32_t fsm[];
    uint32_t* Qs  = fsm;
    uint32_t* Ks0 = Qs  + QS_WORDS;
    uint32_t* Ks1 = Ks0 + KS_WORDS;
    uint32_t* Vs0 = Ks1 + KS_WORDS;
    uint32_t* Vs1 = Vs0 + VS_WORDS;
    uint32_t* Ps  = Vs1 + VS_WORDS;
    float* m_s    = (float*)(Ps + PS_WORDS);
    float* l_s    = m_s + 64;
    float* salpha = l_s + 64;
    float* PsF    = (float*)Ps;

    const int h  = blockIdx.x;
    const int qt = (S_LEN / 64 - 1) - blockIdx.y;
    const int tid = threadIdx.x;
    const int lane = tid & 31;
    const int warp = tid >> 5;
    const int g    = lane >> 2;
    const int tig  = lane & 3;
    const int wr   = warp >> 1;
    const int wc   = warp & 1;
    const int m0   = wr * 16;

    const uint32_t qs_a  = (uint32_t)__cvta_generic_to_shared(Qs);
    const uint32_t ks0_a = (uint32_t)__cvta_generic_to_shared(Ks0);
    const uint32_t ks1_a = (uint32_t)__cvta_generic_to_shared(Ks1);
    const uint32_t vs0_a = (uint32_t)__cvta_generic_to_shared(Vs0);
    const uint32_t vs1_a = (uint32_t)__cvta_generic_to_shared(Vs1);
    const uint32_t ps_a  = (uint32_t)__cvta_generic_to_shared(Ps);

    const float qscale = 0.08838834764831845f;
#pragma unroll
    for (int it = 0; it < 8; it++) {
        int idx = it * 256 + tid;
        int r = idx >> 5;
        int c = (idx & 31) << 2;
        float4 v = *(const float4*)(g_q + (size_t)(qt * 64 + r) * DM + h * HD + c);
        uint4 u;
        u.x = f2tf32(v.x * qscale);
        u.y = f2tf32(v.y * qscale);
        u.z = f2tf32(v.z * qscale);
        u.w = f2tf32(v.w * qscale);
        *(uint4*)&Qs[r * KQSTR + c] = u;
    }
    if (tid < 64) { m_s[tid] = -1e30f; l_s[tid] = 0.f; }

    auto issue_kv = [&](int kt, int b) {
        const int t0 = kt * 64;
        const uint32_t ka = b ? ks1_a : ks0_a;
        const uint32_t va = b ? vs1_a : vs0_a;
#pragma unroll
        for (int it = 0; it < 8; it++) {
            int idx = it * 256 + tid;
            int r = idx >> 5;
            int c = (idx & 31) << 2;
            size_t off = (size_t)(t0 + r) * DM + h * HD + c;
            cp16(ka + (r * KQSTR + c) * 4, g_kc + off);
            cp16(va + (r * VSTR  + c) * 4, g_vc + off);
        }
        CP_COMMIT();
    };

    issue_kv(0, 0);

    float oacc[8][4];
#pragma unroll
    for (int nt = 0; nt < 8; nt++)
#pragma unroll
        for (int i = 0; i < 4; i++) oacc[nt][i] = 0.f;

    const int arow  = m0 + (lane & 15);
    const int acolh = (lane >> 2) & 4;
    const int brow  = wc * 32 + (lane & 7) + ((lane >> 1) & 8);
    const int bcolh = (lane >> 1) & 4;

    const int ntiles = 33 + qt;
    int p = 0;
    for (int kt = 0; kt < ntiles; kt++) {
        CP_WAIT0();
        __syncthreads();
        if (kt + 1 < ntiles) issue_kv(kt + 1, p ^ 1);

        const uint32_t ka = p ? ks1_a : ks0_a;
        const uint32_t* Vc = p ? Vs1 : Vs0;

        float sacc[4][4];
#pragma unroll
        for (int nt = 0; nt < 4; nt++)
#pragma unroll
            for (int i = 0; i < 4; i++) sacc[nt][i] = 0.f;

#pragma unroll
        for (int ks = 0; ks < 16; ks++) {
            const int k0 = ks * 8;
            uint32_t a[4], b[2][4];
            ldsm4(a, qs_a + (uint32_t)(arow * KQSTR + k0 + acolh) * 4);
            ldsm4(b[0], ka + (uint32_t)(brow * KQSTR + k0 + bcolh) * 4);
            ldsm4(b[1], ka + (uint32_t)((brow + 16) * KQSTR + k0 + bcolh) * 4);
#pragma unroll
            for (int nt = 0; nt < 4; nt++) {
                uint32_t bb[2] = { b[nt >> 1][(nt & 1) * 2],
                                   b[nt >> 1][(nt & 1) * 2 + 1] };
                mma_tf32(sacc[nt], a, bb);
            }
        }

        const bool diag = (kt == ntiles - 1);
        const int r0 = m0 + g, r1 = m0 + g + 8;
#pragma unroll
        for (int nt = 0; nt < 4; nt++) {
            int col = wc * 32 + nt * 8 + 2 * tig;
            float v0 = sacc[nt][0], v1 = sacc[nt][1];
            float v2 = sacc[nt][2], v3 = sacc[nt][3];
            if (diag) {
                if (col     > r0) v0 = -1e30f;
                if (col + 1 > r0) v1 = -1e30f;
                if (col     > r1) v2 = -1e30f;
                if (col + 1 > r1) v3 = -1e30f;
            }
            *(float2*)&PsF[r0 * PSTR + col] = make_float2(v0, v1);
            *(float2*)&PsF[r1 * PSTR + col] = make_float2(v2, v3);
        }
        __syncthreads();

        {
            const int row = tid >> 2;
            const int qd  = tid & 3;
            float* pr = PsF + row * PSTR + qd * 16;
            float4 x0 = *(float4*)(pr + 0);
            float4 x1 = *(float4*)(pr + 4);
            float4 x2 = *(float4*)(pr + 8);
            float4 x3 = *(float4*)(pr + 12);
            float mp = fmaxf(fmaxf(fmaxf(x0.x, x0.y), fmaxf(x0.z, x0.w)),
                             fmaxf(fmaxf(x1.x, x1.y), fmaxf(x1.z, x1.w)));
            mp = fmaxf(mp, fmaxf(fmaxf(fmaxf(x2.x, x2.y), fmaxf(x2.z, x2.w)),
                                 fmaxf(fmaxf(x3.x, x3.y), fmaxf(x3.z, x3.w))));
            mp = fmaxf(mp, __shfl_xor_sync(0xffffffffu, mp, 1));
            mp = fmaxf(mp, __shfl_xor_sync(0xffffffffu, mp, 2));
            const float mold = m_s[row];
            const float mx = fmaxf(mold, mp);
            float sum;
            {
                uint4 u;
                float s = 0.f;
                float p0, p1, p2, p3;
                p0 = __expf(x0.x - mx); p1 = __expf(x0.y - mx);
                p2 = __expf(x0.z - mx); p3 = __expf(x0.w - mx);
                s += (p0 + p1) + (p2 + p3);
                u.x = f2tf32(p0); u.y = f2tf32(p1); u.z = f2tf32(p2); u.w = f2tf32(p3);
                *(uint4*)(pr + 0) = u;
                p0 = __expf(x1.x - mx); p1 = __expf(x1.y - mx);
                p2 = __expf(x1.z - mx); p3 = __expf(x1.w - mx);
                s += (p0 + p1) + (p2 + p3);
                u.x = f2tf32(p0); u.y = f2tf32(p1); u.z = f2tf32(p2); u.w = f2tf32(p3);
                *(uint4*)(pr + 4) = u;
                p0 = __expf(x2.x - mx); p1 = __expf(x2.y - mx);
                p2 = __expf(x2.z - mx); p3 = __expf(x2.w - mx);
                s += (p0 + p1) + (p2 + p3);
                u.x = f2tf32(p0); u.y = f2tf32(p1); u.z = f2tf32(p2); u.w = f2tf32(p3);
                *(uint4*)(pr + 8) = u;
                p0 = __expf(x3.x - mx); p1 = __expf(x3.y - mx);
                p2 = __expf(x3.z - mx); p3 = __expf(x3.w - mx);
                s += (p0 + p1) + (p2 + p3);
                u.x = f2tf32(p0); u.y = f2tf32(p1); u.z = f2tf32(p2); u.w = f2tf32(p3);
                *(uint4*)(pr + 12) = u;
                sum = s;
            }
            sum += __shfl_xor_sync(0xffffffffu, sum, 1);
            sum += __shfl_xor_sync(0xffffffffu, sum, 2);
            __syncwarp();
            if (qd == 0) {
                float alpha = __expf(mold - mx);
                l_s[row] = l_s[row] * alpha + sum;
                m_s[row] = mx;
                salpha[row] = alpha;
            }
        }
        __syncthreads();

        {
            const float alo = salpha[m0 + g];
            const float ahi = salpha[m0 + g + 8];
#pragma unroll
            for (int nt = 0; nt < 8; nt++) {
                oacc[nt][0] *= alo; oacc[nt][1] *= alo;
                oacc[nt][2] *= ahi; oacc[nt][3] *= ahi;
            }
#pragma unroll
            for (int ks = 0; ks < 8; ks++) {
                const int k0 = ks * 8;
                uint32_t a[4];
                ldsm4(a, ps_a + (uint32_t)(arow * PSTR + k0 + acolh) * 4);
                const uint32_t* V0 = Vc + (k0 + tig) * VSTR + wc * 64 + g;
                const uint32_t* V1 = V0 + 4 * VSTR;
#pragma unroll
                for (int nt = 0; nt < 8; nt++) {
                    uint32_t b[2];
                    b[0] = V0[nt * 8];
                    b[1] = V1[nt * 8];
                    mma_tf32(oacc[nt], a, b);
                }
            }
        }
        p ^= 1;
    }

    __syncthreads();
    const float ilo = 1.f / l_s[m0 + g];
    const float ihi = 1.f / l_s[m0 + g + 8];
    const int grow = qt * 64 + m0 + g;
#pragma unroll
    for (int nt = 0; nt < 8; nt++) {
        const int col = h * HD + wc * 64 + nt * 8 + 2 * tig;
        uint32_t* d0 = (uint32_t*)(g_at + (size_t)grow * DM + col);
        uint32_t* d1 = (uint32_t*)(g_at + (size_t)(grow + 8) * DM + col);
        d0[0] = f2tf32(oacc[nt][0] * ilo);
        d0[1] = f2tf32(oacc[nt][1] * ilo);
        d1[0] = f2tf32(oacc[nt][2] * ihi);
        d1[1] = f2tf32(oacc[nt][3] * ihi);
    }
}

// ---------------------------------------------------------------------------
// Launch
// ---------------------------------------------------------------------------
extern "C" void kernel_launch(void* const* d_in, const int* in_sizes, int n_in,
                              void* d_out, int out_size)
{
    (void)in_sizes; (void)n_in; (void)out_size;
    const float* xs      = (const float*)d_in[0];
    const float* cache_k = (const float*)d_in[1];
    const float* cache_v = (const float*)d_in[2];
    const float* norm_w  = (const float*)d_in[3];
    const float* wq      = (const float*)d_in[4];
    const float* wk      = (const float*)d_in[5];
    const float* wv      = (const float*)d_in[6];
    const float* wo      = (const float*)d_in[7];
    float* out = (float*)d_out;

    float *p_xn, *p_q, *p_at, *p_vc, *p_wqkv, *p_woc;
    cudaGetSymbolAddress((void**)&p_xn, g_xn);
    cudaGetSymbolAddress((void**)&p_q,  g_q);
    cudaGetSymbolAddress((void**)&p_at, g_at);
    cudaGetSymbolAddress((void**)&p_vc, g_vc);
    cudaGetSymbolAddress((void**)&p_wqkv, g_wqkv);
    cudaGetSymbolAddress((void**)&p_woc, g_woc);

    cudaFuncSetAttribute((const void*)&sgemm_tc<true, false>,
                         cudaFuncAttributeMaxDynamicSharedMemorySize,
                         GEMM_SMEM_BYTES);
    cudaFuncSetAttribute((const void*)&sgemm_tc<false, false>,
                         cudaFuncAttributeMaxDynamicSharedMemorySize,
                         GEMM_SMEM_BYTES);
    cudaFuncSetAttribute((const void*)&flash_tc_kernel,
                         cudaFuncAttributeMaxDynamicSharedMemorySize,
                         FLASH_SMEM_BYTES);

    // 1) RMSNorm (emits tf32-rounded xn)
    rmsnorm_kernel<<<S_LEN, 256>>>(xs, norm_w);

    // 2) Weight conversion to tf32 (stacked qkv + wo)
    {
        const size_t n4 = (size_t)4 * DM * DM / 4;
        convert_w_kernel<<<(unsigned)(n4 / 256), 256>>>(wq, wk, wv, wo);
    }

    // 3) KV-cache conversion
    {
        const size_t n4 = (size_t)CACHE * DM / 4;
        convert_kv_cache_kernel<<<(unsigned)(n4 / 256), 256>>>(cache_k, cache_v);
    }

    // 4) Fused QKV projection: one launch, 768 CTAs.
    //    q -> g_q, k -> g_k, v -> rounded into g_vc[CACHE:].
    {
        dim3 gq(3 * DM / 128, S_LEN / 128);   // (96, 8)
        sgemm_tc<true, false><<<gq, 256, GEMM_SMEM_BYTES>>>(
            p_xn, p_wqkv, p_q, p_vc + (size_t)CACHE * DM, DM, DM);
    }

    // 5) RoPE: q in-place; k -> rounded into g_kc[CACHE:]
    const int rope_threads = S_LEN * NH * 64;
    rope_q_kernel<<<rope_threads / 256, 256>>>();
    rope_k_kernel<<<rope_threads / 256, 256>>>();

    // 6) Tensor-core flash attention (512 one-job blocks, long first)
    flash_tc_kernel<<<dim3(NH, S_LEN / 64), 256, FLASH_SMEM_BYTES>>>();

    // 7) Output projection -> d_out
    {
        dim3 gg(DM / 128, S_LEN / 128);
        sgemm_tc<false, false><<<gg, 256, GEMM_SMEM_BYTES>>>(
            p_at, p_woc, out, nullptr, DM, DM);
    }
}

// round 11
// speedup vs baseline: 1.0725x; 1.0342x over previous
#include <cuda_runtime.h>
#include <math.h>
#include <stdint.h>

// Problem constants (fixed shapes for this problem instance)
#define S_LEN  1024
#define DM     4096
#define NH     32
#define HD     128
#define CACHE  2048
#define TTOT   (CACHE + S_LEN)   // 3072 total kv positions

// Scratch (device globals: allocation-free rule)
__device__ float g_xn[S_LEN * DM];
__device__ float g_q [S_LEN * DM];
__device__ float g_k [S_LEN * DM];
__device__ float g_at[S_LEN * DM];
__device__ float g_kc[(size_t)TTOT * DM];   // tf32-rounded unified K [T,H,HD]
__device__ float g_vc[(size_t)TTOT * DM];   // tf32-rounded unified V [T,H,HD]

// ---------------------------------------------------------------------------
// Common tensor-core helpers
// ---------------------------------------------------------------------------
__device__ __forceinline__ uint32_t f2tf32(float x) {
    uint32_t r;
    asm("cvt.rna.tf32.f32 %0, %1;" : "=r"(r) : "f"(x));
    return r;
}
__device__ __forceinline__ uint32_t u2tf32(uint32_t x) {
    uint32_t r;
    asm("cvt.rna.tf32.f32 %0, %1;" : "=r"(r) : "r"(x));
    return r;
}

__device__ __forceinline__ void mma_tf32(float c[4], const uint32_t a[4], const uint32_t b[2]) {
    asm volatile(
        "mma.sync.aligned.m16n8k8.row.col.f32.tf32.tf32.f32 "
        "{%0,%1,%2,%3}, {%4,%5,%6,%7}, {%8,%9}, {%0,%1,%2,%3};"
        : "+f"(c[0]), "+f"(c[1]), "+f"(c[2]), "+f"(c[3])
        : "r"(a[0]), "r"(a[1]), "r"(a[2]), "r"(a[3]), "r"(b[0]), "r"(b[1]));
}

__device__ __forceinline__ void ldsm4(uint32_t r[4], uint32_t addr) {
    asm volatile("ldmatrix.sync.aligned.m8n8.x4.shared.b16 {%0,%1,%2,%3}, [%4];"
        : "=r"(r[0]), "=r"(r[1]), "=r"(r[2]), "=r"(r[3]) : "r"(addr));
}

__device__ __forceinline__ void cp16(uint32_t dst, const void* src) {
    asm volatile("cp.async.cg.shared.global [%0], [%1], 16;" :: "r"(dst), "l"(src));
}
#define CP_COMMIT()  asm volatile("cp.async.commit_group;")
#define CP_WAIT0()   asm volatile("cp.async.wait_group 0;")
#define CP_WAIT1()   asm volatile("cp.async.wait_group 1;")

// ---------------------------------------------------------------------------
// RMSNorm: one block per row (4096 elems), 256 threads. Emits rna tf32.
// ---------------------------------------------------------------------------
__global__ void rmsnorm_kernel(const float* __restrict__ xs,
                               const float* __restrict__ w)
{
    const int row = blockIdx.x;
    const int tid = threadIdx.x;
    const float* x = xs + (size_t)row * DM;
    float* y = g_xn + (size_t)row * DM;

    float ss = 0.f;
#pragma unroll
    for (int i = 0; i < 4; i++) {
        float4 v = *(const float4*)(x + (i * 256 + tid) * 4);
        ss += v.x * v.x + v.y * v.y + v.z * v.z + v.w * v.w;
    }
#pragma unroll
    for (int off = 16; off; off >>= 1)
        ss += __shfl_xor_sync(0xffffffffu, ss, off);

    __shared__ float red[8];
    __shared__ float s_inv;
    if ((tid & 31) == 0) red[tid >> 5] = ss;
    __syncthreads();
    if (tid == 0) {
        float t = 0.f;
#pragma unroll
        for (int i = 0; i < 8; i++) t += red[i];
        s_inv = rsqrtf(t / (float)DM + 1e-6f);
    }
    __syncthreads();
    const float inv = s_inv;
#pragma unroll
    for (int i = 0; i < 4; i++) {
        int base = (i * 256 + tid) * 4;
        float4 v = *(const float4*)(x + base);
        float4 g = *(const float4*)(w + base);
        uint4 u;
        u.x = f2tf32(v.x * inv * g.x);
        u.y = f2tf32(v.y * inv * g.y);
        u.z = f2tf32(v.z * inv * g.z);
        u.w = f2tf32(v.w * inv * g.w);
        *(uint4*)(y + base) = u;
    }
}

// ---------------------------------------------------------------------------
// TF32 tensor-core GEMM (NT), round-7 proven core: tile 128x128x32,
// 3-stage cp.async, ldmatrix fragments, stride 36.
// B is RAW fp32; B-fragments are RNA-rounded to tf32 in registers after
// ldmatrix (bit-identical to pre-converting the weights, but saves the
// 512MB convert pass). A must be pre-rounded tf32.
// FUSED variant: grid.x covers q|k|v thirds with separate B pointers;
// the V third is RNA-rounded on store (feeds flash as mma operand).
// ---------------------------------------------------------------------------
#define GSTR 36
#define ATW  (128 * GSTR)
#define STW  (2 * ATW)
#define NST  3
#define GEMM_SMEM_BYTES (NST * STW * 4)   // 110592 B

template <bool FUSED>
__global__ void __launch_bounds__(256, 2)
sgemm_tc(const float* __restrict__ A,
         const float* __restrict__ B0, const float* __restrict__ B1,
         const float* __restrict__ B2,
         float* __restrict__ C0, float* __restrict__ CV, int N, int K)
{
    extern __shared__ uint32_t gsm[];
    const uint32_t sbase = (uint32_t)__cvta_generic_to_shared(gsm);

    const int tid  = threadIdx.x;
    const int lane = tid & 31;
    const int warp = tid >> 5;
    const int g    = lane >> 2;
    const int tig  = lane & 3;
    const int m_base = (warp >> 2) * 64;
    const int n_base = (warp & 3) * 32;

    const float* B = B0;
    float* C = C0;
    int bxx = blockIdx.x;
    bool round_out = false;
    if (FUSED) {
        const int third = blockIdx.x >> 5;       // 0:q 1:k 2:v
        bxx = blockIdx.x & 31;
        if (third == 1)      { B = B1; C = g_k; }
        else if (third == 2) { B = B2; C = CV; round_out = true; }
    }

    const int r0 = tid >> 3;
    const int c0 = (tid & 7) << 2;
    const float* Ag = A + (size_t)(blockIdx.y * 128 + r0) * K + c0;
    const float* Bg = B + (size_t)(bxx * 128 + r0) * K + c0;
    const uint32_t d0 = (uint32_t)(r0 * GSTR + c0) * 4;
    const size_t gstep = (size_t)32 * K;
    const uint32_t sstep = (uint32_t)(32 * GSTR) * 4;

    auto issue = [&](int kt) {
        const uint32_t st = sbase + (uint32_t)(kt % NST) * (STW * 4);
        const int ko = kt << 5;
        const float* a = Ag + ko;
        const float* b = Bg + ko;
#pragma unroll
        for (int it = 0; it < 4; it++) {
            cp16(st + d0 + it * sstep, a + it * gstep);
            cp16(st + ATW * 4 + d0 + it * sstep, b + it * gstep);
        }
        CP_COMMIT();
    };

    float c[4][4][4];
#pragma unroll
    for (int mt = 0; mt < 4; mt++)
#pragma unroll
        for (int nt = 0; nt < 4; nt++)
#pragma unroll
            for (int i = 0; i < 4; i++) c[mt][nt][i] = 0.f;

    issue(0); issue(1);

    const int arow  = m_base + (lane & 15);
    const int acolh = (lane >> 2) & 4;
    const int brow  = n_base + (lane & 7) + ((lane >> 1) & 8);
    const int bcolh = (lane >> 1) & 4;

    const int KT = K >> 5;
    for (int kt = 0; kt < KT; kt++) {
        if (kt + 1 < KT) { CP_WAIT1(); } else { CP_WAIT0(); }
        __syncthreads();
        if (kt + 2 < KT) issue(kt + 2);

        const uint32_t tA = sbase + (uint32_t)(kt % NST) * (STW * 4);
        const uint32_t tB = tA + ATW * 4;
#pragma unroll
        for (int kk = 0; kk < 4; kk++) {
            uint32_t a[4][4], b[2][4];
#pragma unroll
            for (int mt = 0; mt < 4; mt++)
                ldsm4(a[mt], tA + (uint32_t)((arow + mt * 16) * GSTR + kk * 8 + acolh) * 4);
            ldsm4(b[0], tB + (uint32_t)(brow * GSTR + kk * 8 + bcolh) * 4);
            ldsm4(b[1], tB + (uint32_t)((brow + 16) * GSTR + kk * 8 + bcolh) * 4);
            // Round raw fp32 B fragments to tf32 (rna) in registers.
#pragma unroll
            for (int i = 0; i < 4; i++) {
                b[0][i] = u2tf32(b[0][i]);
                b[1][i] = u2tf32(b[1][i]);
            }
#pragma unroll
            for (int mt = 0; mt < 4; mt++)
#pragma unroll
                for (int nt = 0; nt < 4; nt++) {
                    uint32_t bb[2] = { b[nt >> 1][(nt & 1) * 2],
                                       b[nt >> 1][(nt & 1) * 2 + 1] };
                    mma_tf32(c[mt][nt], a[mt], bb);
                }
        }
    }

    const int crow = blockIdx.y * 128 + m_base + g;
    const int ccol = bxx * 128 + n_base + 2 * tig;
#pragma unroll
    for (int mt = 0; mt < 4; mt++) {
#pragma unroll
        for (int nt = 0; nt < 4; nt++) {
            const int row = crow + mt * 16;
            const int col = ccol + nt * 8;
            if (FUSED && round_out) {
                uint32_t* p0 = (uint32_t*)(C + (size_t)row * N + col);
                uint32_t* p1 = (uint32_t*)(C + (size_t)(row + 8) * N + col);
                p0[0] = f2tf32(c[mt][nt][0]);
                p0[1] = f2tf32(c[mt][nt][1]);
                p1[0] = f2tf32(c[mt][nt][2]);
                p1[1] = f2tf32(c[mt][nt][3]);
            } else {
                *(float2*)(C + (size_t)row * N + col) =
                    make_float2(c[mt][nt][0], c[mt][nt][1]);
                *(float2*)(C + (size_t)(row + 8) * N + col) =
                    make_float2(c[mt][nt][2], c[mt][nt][3]);
            }
        }
    }
}

// ---------------------------------------------------------------------------
// RoPE. rope_q: in-place on g_q (raw fp32). rope_k: g_k -> g_kc[CACHE:],
// RNA-rounded.
// ---------------------------------------------------------------------------
__global__ void rope_q_kernel()
{
    int idx = blockIdx.x * blockDim.x + threadIdx.x;
    int i = idx & 63;
    int h = (idx >> 6) & (NH - 1);
    int s = idx >> 11;

    float pos = (float)(s + CACHE);
    float inv_freq = exp2f(-(float)i * (13.287712379549449f / 64.f));
    float ang = pos * inv_freq;
    float sn, cs;
    sincosf(ang, &sn, &cs);

    float* p = g_q + ((size_t)(s * NH + h) * HD) + i;
    float x1 = p[0];
    float x2 = p[64];
    p[0]  = x1 * cs - x2 * sn;
    p[64] = x2 * cs + x1 * sn;
}

__global__ void rope_k_kernel()
{
    int idx = blockIdx.x * blockDim.x + threadIdx.x;
    int i = idx & 63;
    int h = (idx >> 6) & (NH - 1);
    int s = idx >> 11;

    float pos = (float)(s + CACHE);
    float inv_freq = exp2f(-(float)i * (13.287712379549449f / 64.f));
    float ang = pos * inv_freq;
    float sn, cs;
    sincosf(ang, &sn, &cs);

    const float* p = g_k + ((size_t)(s * NH + h) * HD) + i;
    float x1 = p[0];
    float x2 = p[64];
    uint32_t* d = (uint32_t*)(g_kc + (size_t)(CACHE + s) * DM + h * HD + i);
    d[0]  = f2tf32(x1 * cs - x2 * sn);
    d[64] = f2tf32(x2 * cs + x1 * sn);
}

// ---------------------------------------------------------------------------
// Convert the KV-cache part (t < CACHE) into RNA-rounded tf32 buffers.
// ---------------------------------------------------------------------------
__global__ void convert_kv_cache_kernel(const float* __restrict__ cache_k,
                                        const float* __restrict__ cache_v)
{
    const size_t elem = ((size_t)blockIdx.x * blockDim.x + threadIdx.x) * 4;
    float4 k = *(const float4*)(cache_k + elem);
    float4 v = *(const float4*)(cache_v + elem);
    uint4 ko, vo;
    ko.x = f2tf32(k.x); ko.y = f2tf32(k.y); ko.z = f2tf32(k.z); ko.w = f2tf32(k.w);
    vo.x = f2tf32(v.x); vo.y = f2tf32(v.y); vo.z = f2tf32(v.z); vo.w = f2tf32(v.w);
    *(uint4*)(g_kc + elem) = ko;
    *(uint4*)(g_vc + elem) = vo;
}

// ---------------------------------------------------------------------------
// Tensor-core flash attention (round-7 proven: 512 one-job blocks, long
// jobs first).
// ---------------------------------------------------------------------------
#define KQSTR 132
#define VSTR  136
#define PSTR  68

#define QS_WORDS (64 * KQSTR)
#define KS_WORDS (64 * KQSTR)
#define VS_WORDS (64 * VSTR)
#define PS_WORDS (64 * PSTR)

#define FLASH_SMEM_WORDS (QS_WORDS + 2*KS_WORDS + 2*VS_WORDS + PS_WORDS + 192)
#define FLASH_SMEM_BYTES (FLASH_SMEM_WORDS * 4)

__global__ void __launch_bounds__(256, 1)
flash_tc_kernel()
{
    extern __shared__ uint32_t fsm[];
    uint32_t* Qs  = fsm;
    uint32_t* Ks0 = Qs  + QS_WORDS;
    uint32_t* Ks1 = Ks0 + KS_WORDS;
    uint32_t* Vs0 = Ks1 + KS_WORDS;
    uint32_t* Vs1 = Vs0 + VS_WORDS;
    uint32_t* Ps  = Vs1 + VS_WORDS;
    float* m_s    = (float*)(Ps + PS_WORDS);
    float* l_s    = m_s + 64;
    float* salpha = l_s + 64;
    float* PsF    = (float*)Ps;

    const int h  = blockIdx.x;
    const int qt = (S_LEN / 64 - 1) - blockIdx.y;
    const int tid = threadIdx.x;
    const int lane = tid & 31;
    const int warp = tid >> 5;
    const int g    = lane >> 2;
    const int tig  = lane & 3;
    const int wr   = warp >> 1;
    const int wc   = warp & 1;
    const int m0   = wr * 16;

    const uint32_t qs_a  = (uint32_t)__cvta_generic_to_shared(Qs);
    const uint32_t ks0_a = (uint32_t)__cvta_generic_to_shared(Ks0);
    const uint32_t ks1_a = (uint32_t)__cvta_generic_to_shared(Ks1);
    const uint32_t vs0_a = (uint32_t)__cvta_generic_to_shared(Vs0);
    const uint32_t vs1_a = (uint32_t)__cvta_generic_to_shared(Vs1);
    const uint32_t ps_a  = (uint32_t)__cvta_generic_to_shared(Ps);

    const float qscale = 0.08838834764831845f;
#pragma unroll
    for (int it = 0; it < 8; it++) {
        int idx = it * 256 + tid;
        int r = idx >> 5;
        int c = (idx & 31) << 2;
        float4 v = *(const float4*)(g_q + (size_t)(qt * 64 + r) * DM + h * HD + c);
        uint4 u;
        u.x = f2tf32(v.x * qscale);
        u.y = f2tf32(v.y * qscale);
        u.z = f2tf32(v.z * qscale);
        u.w = f2tf32(v.w * qscale);
        *(uint4*)&Qs[r * KQSTR + c] = u;
    }
    if (tid < 64) { m_s[tid] = -1e30f; l_s[tid] = 0.f; }

    auto issue_kv = [&](int kt, int b) {
        const int t0 = kt * 64;
        const uint32_t ka = b ? ks1_a : ks0_a;
        const uint32_t va = b ? vs1_a : vs0_a;
#pragma unroll
        for (int it = 0; it < 8; it++) {
            int idx = it * 256 + tid;
            int r = idx >> 5;
            int c = (idx & 31) << 2;
            size_t off = (size_t)(t0 + r) * DM + h * HD + c;
            cp16(ka + (r * KQSTR + c) * 4, g_kc + off);
            cp16(va + (r * VSTR  + c) * 4, g_vc + off);
        }
        CP_COMMIT();
    };

    issue_kv(0, 0);

    float oacc[8][4];
#pragma unroll
    for (int nt = 0; nt < 8; nt++)
#pragma unroll
        for (int i = 0; i < 4; i++) oacc[nt][i] = 0.f;

    const int arow  = m0 + (lane & 15);
    const int acolh = (lane >> 2) & 4;
    const int brow  = wc * 32 + (lane & 7) + ((lane >> 1) & 8);
    const int bcolh = (lane >> 1) & 4;

    const int ntiles = 33 + qt;
    int p = 0;
    for (int kt = 0; kt < ntiles; kt++) {
        CP_WAIT0();
        __syncthreads();
        if (kt + 1 < ntiles) issue_kv(kt + 1, p ^ 1);

        const uint32_t ka = p ? ks1_a : ks0_a;
        const uint32_t* Vc = p ? Vs1 : Vs0;

        float sacc[4][4];
#pragma unroll
        for (int nt = 0; nt < 4; nt++)
#pragma unroll
            for (int i = 0; i < 4; i++) sacc[nt][i] = 0.f;

#pragma unroll
        for (int ks = 0; ks < 16; ks++) {
            const int k0 = ks * 8;
            uint32_t a[4], b[2][4];
            ldsm4(a, qs_a + (uint32_t)(arow * KQSTR + k0 + acolh) * 4);
            ldsm4(b[0], ka + (uint32_t)(brow * KQSTR + k0 + bcolh) * 4);
            ldsm4(b[1], ka + (uint32_t)((brow + 16) * KQSTR + k0 + bcolh) * 4);
#pragma unroll
            for (int nt = 0; nt < 4; nt++) {
                uint32_t bb[2] = { b[nt >> 1][(nt & 1) * 2],
                                   b[nt >> 1][(nt & 1) * 2 + 1] };
                mma_tf32(sacc[nt], a, bb);
            }
        }

        const bool diag = (kt == ntiles - 1);
        const int r0 = m0 + g, r1 = m0 + g + 8;
#pragma unroll
        for (int nt = 0; nt < 4; nt++) {
            int col = wc * 32 + nt * 8 + 2 * tig;
            float v0 = sacc[nt][0], v1 = sacc[nt][1];
            float v2 = sacc[nt][2], v3 = sacc[nt][3];
            if (diag) {
                if (col     > r0) v0 = -1e30f;
                if (col + 1 > r0) v1 = -1e30f;
                if (col     > r1) v2 = -1e30f;
                if (col + 1 > r1) v3 = -1e30f;
            }
            *(float2*)&PsF[r0 * PSTR + col] = make_float2(v0, v1);
            *(float2*)&PsF[r1 * PSTR + col] = make_float2(v2, v3);
        }
        __syncthreads();

        {
            const int row = tid >> 2;
            const int qd  = tid & 3;
            float* pr = PsF + row * PSTR + qd * 16;
            float4 x0 = *(float4*)(pr + 0);
            float4 x1 = *(float4*)(pr + 4);
            float4 x2 = *(float4*)(pr + 8);
            float4 x3 = *(float4*)(pr + 12);
            float mp = fmaxf(fmaxf(fmaxf(x0.x, x0.y), fmaxf(x0.z, x0.w)),
                             fmaxf(fmaxf(x1.x, x1.y), fmaxf(x1.z, x1.w)));
            mp = fmaxf(mp, fmaxf(fmaxf(fmaxf(x2.x, x2.y), fmaxf(x2.z, x2.w)),
                                 fmaxf(fmaxf(x3.x, x3.y), fmaxf(x3.z, x3.w))));
            mp = fmaxf(mp, __shfl_xor_sync(0xffffffffu, mp, 1));
            mp = fmaxf(mp, __shfl_xor_sync(0xffffffffu, mp, 2));
            const float mold = m_s[row];
            const float mx = fmaxf(mold, mp);
            float sum;
            {
                uint4 u;
                float s = 0.f;
                float p0, p1, p2, p3;
                p0 = __expf(x0.x - mx); p1 = __expf(x0.y - mx);
                p2 = __expf(x0.z - mx); p3 = __expf(x0.w - mx);
                s += (p0 + p1) + (p2 + p3);
                u.x = f2tf32(p0); u.y = f2tf32(p1); u.z = f2tf32(p2); u.w = f2tf32(p3);
                *(uint4*)(pr + 0) = u;
                p0 = __expf(x1.x - mx); p1 = __expf(x1.y - mx);
                p2 = __expf(x1.z - mx); p3 = __expf(x1.w - mx);
                s += (p0 + p1) + (p2 + p3);
                u.x = f2tf32(p0); u.y = f2tf32(p1); u.z = f2tf32(p2); u.w = f2tf32(p3);
                *(uint4*)(pr + 4) = u;
                p0 = __expf(x2.x - mx); p1 = __expf(x2.y - mx);
                p2 = __expf(x2.z - mx); p3 = __expf(x2.w - mx);
                s += (p0 + p1) + (p2 + p3);
                u.x = f2tf32(p0); u.y = f2tf32(p1); u.z = f2tf32(p2); u.w = f2tf32(p3);
                *(uint4*)(pr + 8) = u;
                p0 = __expf(x3.x - mx); p1 = __expf(x3.y - mx);
                p2 = __expf(x3.z - mx); p3 = __expf(x3.w - mx);
                s += (p0 + p1) + (p2 + p3);
                u.x = f2tf32(p0); u.y = f2tf32(p1); u.z = f2tf32(p2); u.w = f2tf32(p3);
                *(uint4*)(pr + 12) = u;
                sum = s;
            }
            sum += __shfl_xor_sync(0xffffffffu, sum, 1);
            sum += __shfl_xor_sync(0xffffffffu, sum, 2);
            __syncwarp();
            if (qd == 0) {
                float alpha = __expf(mold - mx);
                l_s[row] = l_s[row] * alpha + sum;
                m_s[row] = mx;
                salpha[row] = alpha;
            }
        }
        __syncthreads();

        {
            const float alo = salpha[m0 + g];
            const float ahi = salpha[m0 + g + 8];
#pragma unroll
            for (int nt = 0; nt < 8; nt++) {
                oacc[nt][0] *= alo; oacc[nt][1] *= alo;
                oacc[nt][2] *= ahi; oacc[nt][3] *= ahi;
            }
#pragma unroll
            for (int ks = 0; ks < 8; ks++) {
                const int k0 = ks * 8;
                uint32_t a[4];
                ldsm4(a, ps_a + (uint32_t)(arow * PSTR + k0 + acolh) * 4);
                const uint32_t* V0 = Vc + (k0 + tig) * VSTR + wc * 64 + g;
                const uint32_t* V1 = V0 + 4 * VSTR;
#pragma unroll
                for (int nt = 0; nt < 8; nt++) {
                    uint32_t b[2];
                    b[0] = V0[nt * 8];
                    b[1] = V1[nt * 8];
                    mma_tf32(oacc[nt], a, b);
                }
            }
        }
        p ^= 1;
    }

    __syncthreads();
    const float ilo = 1.f / l_s[m0 + g];
    const float ihi = 1.f / l_s[m0 + g + 8];
    const int grow = qt * 64 + m0 + g;
#pragma unroll
    for (int nt = 0; nt < 8; nt++) {
        const int col = h * HD + wc * 64 + nt * 8 + 2 * tig;
        uint32_t* d0 = (uint32_t*)(g_at + (size_t)grow * DM + col);
        uint32_t* d1 = (uint32_t*)(g_at + (size_t)(grow + 8) * DM + col);
        d0[0] = f2tf32(oacc[nt][0] * ilo);
        d0[1] = f2tf32(oacc[nt][1] * ilo);
        d1[0] = f2tf32(oacc[nt][2] * ihi);
        d1[1] = f2tf32(oacc[nt][3] * ihi);
    }
}

// ---------------------------------------------------------------------------
// Launch
// ---------------------------------------------------------------------------
extern "C" void kernel_launch(void* const* d_in, const int* in_sizes, int n_in,
                              void* d_out, int out_size)
{
    (void)in_sizes; (void)n_in; (void)out_size;
    const float* xs      = (const float*)d_in[0];
    const float* cache_k = (const float*)d_in[1];
    const float* cache_v = (const float*)d_in[2];
    const float* norm_w  = (const float*)d_in[3];
    const float* wq      = (const float*)d_in[4];
    const float* wk      = (const float*)d_in[5];
    const float* wv      = (const float*)d_in[6];
    const float* wo      = (const float*)d_in[7];
    float* out = (float*)d_out;

    float *p_xn, *p_q, *p_at, *p_vc;
    cudaGetSymbolAddress((void**)&p_xn, g_xn);
    cudaGetSymbolAddress((void**)&p_q,  g_q);
    cudaGetSymbolAddress((void**)&p_at, g_at);
    cudaGetSymbolAddress((void**)&p_vc, g_vc);

    cudaFuncSetAttribute((const void*)&sgemm_tc<true>,
                         cudaFuncAttributeMaxDynamicSharedMemorySize,
                         GEMM_SMEM_BYTES);
    cudaFuncSetAttribute((const void*)&sgemm_tc<false>,
                         cudaFuncAttributeMaxDynamicSharedMemorySize,
                         GEMM_SMEM_BYTES);
    cudaFuncSetAttribute((const void*)&flash_tc_kernel,
                         cudaFuncAttributeMaxDynamicSharedMemorySize,
                         FLASH_SMEM_BYTES);

    // 1) RMSNorm (emits tf32-rounded xn)
    rmsnorm_kernel<<<S_LEN, 256>>>(xs, norm_w);

    // 2) KV-cache conversion
    {
        const size_t n4 = (size_t)CACHE * DM / 4;
        convert_kv_cache_kernel<<<(unsigned)(n4 / 256), 256>>>(cache_k, cache_v);
    }

    // 3) Fused QKV projection: one launch, 768 CTAs, raw weights
    //    (B rounded in-register). q -> g_q, k -> g_k, v -> g_vc[CACHE:].
    {
        dim3 gq(3 * DM / 128, S_LEN / 128);   // (96, 8)
        sgemm_tc<true><<<gq, 256, GEMM_SMEM_BYTES>>>(
            p_xn, wq, wk, wv, p_q, p_vc + (size_t)CACHE * DM, DM, DM);
    }

    // 4) RoPE: q in-place; k -> rounded into g_kc[CACHE:]
    const int rope_threads = S_LEN * NH * 64;
    rope_q_kernel<<<rope_threads / 256, 256>>>();
    rope_k_kernel<<<rope_threads / 256, 256>>>();

    // 5) Tensor-core flash attention (512 one-job blocks, long first)
    flash_tc_kernel<<<dim3(NH, S_LEN / 64), 256, FLASH_SMEM_BYTES>>>();

    // 6) Output projection -> d_out (raw wo, B rounded in-register)
    {
        dim3 gg(DM / 128, S_LEN / 128);
        sgemm_tc<false><<<gg, 256, GEMM_SMEM_BYTES>>>(
            p_at, wo, nullptr, nullptr, out, nullptr, DM, DM);
    }
}